// round 3
// baseline (speedup 1.0000x reference)
#include <cuda_runtime.h>
#include <cstdint>

// Problem constants (fixed by the reference setup)
#define BB 32
#define SS 32
#define AA 512
#define VOCAB 32000
#define WPB (VOCAB / 32)    // 1000 bitmap words per batch
#define CPR (VOCAB / 16)    // 2000 16-elem chunks per (b,s) row

// Scratch (device globals — no allocation allowed)
__device__ int      g_slotmap[BB * VOCAB];  // head a-index per (b, vocab), -1 = none (4 MB)
__device__ unsigned g_bitmap [BB * WPB];    // 1 bit per (b, vocab) hit       (128 KB)
__device__ int      g_chain  [BB * AA];     // collision chain per (b, a)     (64 KB)

// ---------------------------------------------------------------------------
// Kernel 0: re-initialize slotmap (-1) and bitmap (0) every launch.
// Stale slotmap heads across graph replays would corrupt the chains.
// ---------------------------------------------------------------------------
__global__ void __launch_bounds__(256)
pg_init_kernel() {
    int idx = blockIdx.x * blockDim.x + threadIdx.x;
    const int nslot4 = BB * VOCAB / 4;   // 256000 int4 stores
    const int nbm4   = BB * WPB  / 4;    // 8000 int4 stores
    if (idx < nslot4) {
        ((int4*)g_slotmap)[idx] = make_int4(-1, -1, -1, -1);
    } else if (idx < nslot4 + nbm4) {
        ((int4*)g_bitmap)[idx - nslot4] = make_int4(0, 0, 0, 0);
    }
}

// ---------------------------------------------------------------------------
// Kernel 1: build the inverted scatter structure.
// For each (b,a): m = table[seq[b,a]]; skip m==1 (its column is zeroed last
// in the reference, so contributions there are dead). Record hit bit and
// chain this a onto the per-(b,m) list via atomicExch.
// ---------------------------------------------------------------------------
__global__ void __launch_bounds__(256)
pg_build_kernel(const int* __restrict__ seq, const int* __restrict__ tbl) {
    int tid = blockIdx.x * blockDim.x + threadIdx.x;   // 0 .. B*A-1 = 16383
    int b = tid >> 9;           // / AA
    int m = tbl[seq[tid]];
    if (m != 1) {
        atomicOr(&g_bitmap[b * WPB + (m >> 5)], 1u << (m & 31));
        int old = atomicExch(&g_slotmap[b * VOCAB + m], tid & (AA - 1));
        g_chain[tid] = old;
    }
}

// ---------------------------------------------------------------------------
// Kernel 2: fused copy + gather-max + zero(col 1).
// Each thread handles 16 consecutive vocab elements of one (b,s) row:
//   4 independent float4 loads (MLP=4), one bitmap-word probe, and — only
//   for set bits — a bounded chain walk folding max(att[row][a]) in regs.
// Streaming hints keep the 262 MB bulk traffic from evicting the small
// bitmap/slotmap/att working set out of L2.
// ---------------------------------------------------------------------------
__global__ void __launch_bounds__(256)
pg_fused_kernel(const float4* __restrict__ src,
                const float*  __restrict__ att,
                float4*       __restrict__ dst) {
    unsigned t   = blockIdx.x * blockDim.x + threadIdx.x;  // 0 .. 2,048,000-1
    unsigned row = t / CPR;              // (b*S + s)
    unsigned c   = t - row * CPR;        // chunk within row, 0..1999
    unsigned b   = row >> 5;             // / SS
    unsigned v0  = c * 16;               // first vocab index of this chunk
    size_t   q0  = (size_t)row * (VOCAB / 4) + c * 4;

    union { float4 q[4]; float f[16]; } u;
    u.q[0] = __ldcs(src + q0 + 0);
    u.q[1] = __ldcs(src + q0 + 1);
    u.q[2] = __ldcs(src + q0 + 2);
    u.q[3] = __ldcs(src + q0 + 3);

    unsigned word = g_bitmap[b * WPB + (v0 >> 5)];
    unsigned m16  = (word >> (v0 & 16)) & 0xFFFFu;

    if (m16) {
        const float* att_row  = att + (size_t)row * AA;
        const int*   slot_v   = g_slotmap + (size_t)b * VOCAB + v0;
        const int*   chain_b  = g_chain + (b << 9);
        #pragma unroll
        for (int j = 0; j < 16; j++) {
            if (m16 & (1u << j)) {
                int   a     = slot_v[j];
                float mv    = u.f[j];
                int   guard = AA;        // hard bound: a hang is impossible
                while (a >= 0 && guard-- > 0) {
                    mv = fmaxf(mv, __ldg(att_row + a));
                    a  = chain_b[a];
                }
                u.f[j] = mv;
            }
        }
    }

    if (c == 0) u.f[1] = 0.0f;   // out[:, :, 1] = 0 (post-max in reference;
                                 // equivalent since m==1 scatters are skipped)

    __stcs(dst + q0 + 0, u.q[0]);
    __stcs(dst + q0 + 1, u.q[1]);
    __stcs(dst + q0 + 2, u.q[2]);
    __stcs(dst + q0 + 3, u.q[3]);
}

// ---------------------------------------------------------------------------
// Launch
// Inputs (metadata order):
//   d_in[0] decoder_outputs  f32 [B,S,VOCAB]
//   d_in[1] attention_scores f32 [B,S,A]
//   d_in[2] input_sequence   i32 [B,A]
//   d_in[3] repeat_idx       i32 [S,1]   (unused)
//   d_in[4] repeat_idx2      i32 [B,1]   (unused)
//   d_in[5] convert_table    i32 [SRC_VOCAB]
// Output: f32 [B,S,VOCAB]
// ---------------------------------------------------------------------------
extern "C" void kernel_launch(void* const* d_in, const int* in_sizes, int n_in,
                              void* d_out, int out_size) {
    const float4* dec = (const float4*)d_in[0];
    const float*  att = (const float*)d_in[1];
    const int*    seq = (const int*)d_in[2];
    const int*    tbl = (const int*)d_in[5];
    float4*       out = (float4*)d_out;

    const int ninit = BB * VOCAB / 4 + BB * WPB / 4;   // 264000
    pg_init_kernel<<<(ninit + 255) / 256, 256>>>();

    pg_build_kernel<<<(BB * AA) / 256, 256>>>(seq, tbl);

    const int nthreads = BB * SS * CPR;                 // 2,048,000
    pg_fused_kernel<<<nthreads / 256, 256>>>(dec, att, out);
}

// round 4
// speedup vs baseline: 1.0422x; 1.0422x over previous
#include <cuda_runtime.h>
#include <cstdint>

// Problem constants (fixed by the reference setup)
#define BB 32
#define SS 32
#define AA 512
#define VOCAB 32000

// Precomputed mapped vocab index per (b, a); -1 means "skip" (m == 1).
__device__ int g_m[BB * AA];   // 64 KB, L2-resident

// ---------------------------------------------------------------------------
// Kernel 1: build g_m and zero out[:, :, 1].
// Runs after the bulk memcpy (stream order). Zeroing col 1 here is equivalent
// to the reference's post-max zeroing because the scatter skips m == 1.
// ---------------------------------------------------------------------------
__global__ void __launch_bounds__(256)
pg_build_kernel(const int* __restrict__ seq,
                const int* __restrict__ tbl,
                float*     __restrict__ out) {
    int tid = blockIdx.x * blockDim.x + threadIdx.x;   // 0 .. B*A-1 = 16383
    int m = tbl[seq[tid]];
    g_m[tid] = (m == 1) ? -1 : m;
    if (tid < BB * SS) {
        out[(size_t)tid * VOCAB + 1] = 0.0f;           // out[:, :, 1] = 0
    }
}

// ---------------------------------------------------------------------------
// Kernel 2: scatter-max, one thread per (b, s, a).
// 524,288 threads; att read is perfectly coalesced (a fastest), g_m read is
// coalesced and L1/L2-hot (re-read 32x across s). atomicMax with unused
// result compiles to RED (no return trip). Non-negative floats -> signed-int
// max on the bit pattern is exact (validated rel_err=0 in earlier rounds).
// ---------------------------------------------------------------------------
__global__ void __launch_bounds__(256)
pg_scatter_kernel(const float* __restrict__ att,
                  float*       __restrict__ out) {
    unsigned tid = blockIdx.x * blockDim.x + threadIdx.x;  // 0 .. 524287
    unsigned a  = tid & (AA - 1);
    unsigned bs = tid >> 9;            // b*S + s  (0 .. 1023)
    unsigned b  = bs >> 5;

    int m = g_m[(b << 9) | a];
    if (m >= 0) {
        float v = att[tid];            // att[(b*S+s)*A + a] == att[tid]
        atomicMax((int*)out + (size_t)bs * VOCAB + m, __float_as_int(v));
    }
}

// ---------------------------------------------------------------------------
// Launch
// Inputs (metadata order):
//   d_in[0] decoder_outputs  f32 [B,S,VOCAB]
//   d_in[1] attention_scores f32 [B,S,A]
//   d_in[2] input_sequence   i32 [B,A]
//   d_in[3] repeat_idx       i32 [S,1]   (unused)
//   d_in[4] repeat_idx2      i32 [B,1]   (unused)
//   d_in[5] convert_table    i32 [SRC_VOCAB]
// Output: f32 [B,S,VOCAB]
// ---------------------------------------------------------------------------
extern "C" void kernel_launch(void* const* d_in, const int* in_sizes, int n_in,
                              void* d_out, int out_size) {
    const float* dec = (const float*)d_in[0];
    const float* att = (const float*)d_in[1];
    const int*   seq = (const int*)d_in[2];
    const int*   tbl = (const int*)d_in[5];
    float*       out = (float*)d_out;

    // Bulk copy: vendor D2D copy kernel (graph-capturable, allowed).
    cudaMemcpyAsync(out, dec, (size_t)BB * SS * VOCAB * sizeof(float),
                    cudaMemcpyDeviceToDevice);

    pg_build_kernel<<<(BB * AA) / 256, 256>>>(seq, tbl, out);

    pg_scatter_kernel<<<(BB * SS * AA) / 256, 256>>>(att, out);
}

// round 5
// speedup vs baseline: 1.0672x; 1.0240x over previous
#include <cuda_runtime.h>
#include <cstdint>

// Problem constants (fixed by the reference setup)
#define BB 32
#define SS 32
#define AA 512
#define VOCAB 32000
#define SENTINEL 0x7FFFFFFF

// Per-batch (m,a) pairs packed as (m<<9)|a, sorted ascending by m.
// m==1 entries stored as SENTINEL (sorted to the end, skipped by scatter).
__device__ int g_sorted[BB * AA];   // 64 KB, L2-resident

// ---------------------------------------------------------------------------
// Kernel 1: gather m = table[seq[b,a]] and bitonic-sort the 512 packed
// (m,a) pairs of each batch in shared memory. One block per batch.
// Sorted targets turn the scatter's DRAM pattern from random 32B sectors
// into quasi-sequential ascending addresses (better row locality).
// ---------------------------------------------------------------------------
__global__ void __launch_bounds__(512)
pg_sort_kernel(const int* __restrict__ seq, const int* __restrict__ tbl) {
    __shared__ int sh[AA];
    int b = blockIdx.x;
    int i = threadIdx.x;

    int m = tbl[seq[b * AA + i]];
    sh[i] = (m == 1) ? SENTINEL : ((m << 9) | i);
    __syncthreads();

    // Bitonic sort, 512 elements, 512 threads (each owns element i).
    for (int k = 2; k <= AA; k <<= 1) {
        for (int j = k >> 1; j > 0; j >>= 1) {
            int partner = i ^ j;
            if (partner > i) {
                int x = sh[i], y = sh[partner];
                bool up = ((i & k) == 0);          // ascending segment?
                if ((x > y) == up) { sh[i] = y; sh[partner] = x; }
            }
            __syncthreads();
        }
    }
    g_sorted[b * AA + i] = sh[i];
}

// ---------------------------------------------------------------------------
// Kernel 2: pure streaming copy. 4000 blocks x 512 threads, 4 independent
// float4 per thread (MLP=4), fully coalesced, branchless.
// ---------------------------------------------------------------------------
__global__ void __launch_bounds__(512)
pg_copy_kernel(const float4* __restrict__ src, float4* __restrict__ dst) {
    size_t base = (size_t)blockIdx.x * 2048 + threadIdx.x;
    float4 a = src[base];
    float4 b = src[base + 512];
    float4 c = src[base + 1024];
    float4 d = src[base + 1536];
    dst[base]        = a;
    dst[base + 512]  = b;
    dst[base + 1024] = c;
    dst[base + 1536] = d;
}

// ---------------------------------------------------------------------------
// Kernel 3: sorted scatter-max + zero out[:,:,1].
// tid = (b*S + s)*A + rank. A warp covers 32 consecutive sorted ranks of one
// (b,s) row -> its 32 atomics hit ascending vocab addresses (DRAM-friendly).
// att read is a gathered 2KB/row access (L2-hot). atomicMax result unused
// -> RED, no return trip. Non-negative floats: int max == float max.
// Zeroing col 1 here is safe: no atomic ever targets m==1.
// ---------------------------------------------------------------------------
__global__ void __launch_bounds__(512)
pg_scatter_kernel(const float* __restrict__ att, float* __restrict__ out) {
    unsigned tid  = blockIdx.x * blockDim.x + threadIdx.x;  // 0 .. 524287
    unsigned rank = tid & (AA - 1);
    unsigned bs   = tid >> 9;          // b*S + s  (0 .. 1023)
    unsigned b    = bs >> 5;

    if (tid < BB * SS) {
        out[(size_t)tid * VOCAB + 1] = 0.0f;     // out[:, :, 1] = 0
    }

    int packed = g_sorted[(b << 9) | rank];
    if (packed != SENTINEL) {
        int m = packed >> 9;
        int a = packed & (AA - 1);
        float v = att[(size_t)bs * AA + a];
        atomicMax((int*)out + (size_t)bs * VOCAB + m, __float_as_int(v));
    }
}

// ---------------------------------------------------------------------------
// Launch
// Inputs (metadata order):
//   d_in[0] decoder_outputs  f32 [B,S,VOCAB]
//   d_in[1] attention_scores f32 [B,S,A]
//   d_in[2] input_sequence   i32 [B,A]
//   d_in[3] repeat_idx       i32 [S,1]   (unused)
//   d_in[4] repeat_idx2      i32 [B,1]   (unused)
//   d_in[5] convert_table    i32 [SRC_VOCAB]
// Output: f32 [B,S,VOCAB]
// ---------------------------------------------------------------------------
extern "C" void kernel_launch(void* const* d_in, const int* in_sizes, int n_in,
                              void* d_out, int out_size) {
    const float4* dec = (const float4*)d_in[0];
    const float*  att = (const float*)d_in[1];
    const int*    seq = (const int*)d_in[2];
    const int*    tbl = (const int*)d_in[5];
    float*        out = (float*)d_out;

    pg_sort_kernel<<<BB, AA>>>(seq, tbl);                      // no out dep

    const int n4 = BB * SS * VOCAB / 4;                        // 8,192,000
    pg_copy_kernel<<<n4 / 2048, 512>>>(dec, (float4*)out);

    pg_scatter_kernel<<<(BB * SS * AA) / 512, 512>>>(att, out);
}

// round 6
// speedup vs baseline: 1.2308x; 1.1532x over previous
#include <cuda_runtime.h>
#include <cstdint>

// Problem constants (fixed by the reference setup)
#define BB 32
#define SS 32
#define AA 512
#define VOCAB 32000
#define SENTINEL 0x7FFFFFFF
#define NBKT 128            // bucket = m >> 8 (0..124), sentinel bucket 127

// Per-batch (m,a) pairs packed as (m<<9)|a, bucket-ordered by m>>8.
// m==1 entries stored as SENTINEL at the tail (skipped by scatter).
__device__ int g_sorted[BB * AA];   // 64 KB, L2-resident

// ---------------------------------------------------------------------------
// Kernel 1: gather m = table[seq[b,a]] and counting-sort the 512 packed
// (m,a) pairs of each batch into 128 buckets of m>>8 (256-vocab = 1KB
// granularity). One block per batch, 3 barriers total. Bucket order gives
// the scatter DRAM-row locality; within-bucket order is irrelevant
// (atomics commute).
// ---------------------------------------------------------------------------
__global__ void __launch_bounds__(512)
pg_sort_kernel(const int* __restrict__ seq, const int* __restrict__ tbl) {
    __shared__ int hist[NBKT];
    __shared__ int offs[NBKT];
    int b = blockIdx.x;
    int i = threadIdx.x;

    if (i < NBKT) hist[i] = 0;
    __syncthreads();

    int m = tbl[seq[b * AA + i]];
    int bkt    = (m == 1) ? (NBKT - 1) : (m >> 8);
    int packed = (m == 1) ? SENTINEL   : ((m << 9) | i);
    int rank   = atomicAdd(&hist[bkt], 1);
    __syncthreads();

    // Exclusive scan of 128 bucket counts by warp 0 (4 elems/lane + shfl).
    if (i < 32) {
        int c0 = hist[i * 4 + 0], c1 = hist[i * 4 + 1];
        int c2 = hist[i * 4 + 2], c3 = hist[i * 4 + 3];
        int lsum = c0 + c1 + c2 + c3;
        int pre  = lsum;
        #pragma unroll
        for (int d = 1; d < 32; d <<= 1) {
            int n = __shfl_up_sync(0xFFFFFFFF, pre, d);
            if (i >= d) pre += n;
        }
        pre -= lsum;                       // exclusive prefix of this lane
        offs[i * 4 + 0] = pre;
        offs[i * 4 + 1] = pre + c0;
        offs[i * 4 + 2] = pre + c0 + c1;
        offs[i * 4 + 3] = pre + c0 + c1 + c2;
    }
    __syncthreads();

    g_sorted[b * AA + offs[bkt] + rank] = packed;
}

// ---------------------------------------------------------------------------
// Kernel 2: pure streaming copy. 4 independent float4 per thread (MLP=4),
// fully coalesced, branchless. Streaming (evict-first) hints: the 262MB
// stream should not thrash L2.
// ---------------------------------------------------------------------------
__global__ void __launch_bounds__(512)
pg_copy_kernel(const float4* __restrict__ src, float4* __restrict__ dst) {
    size_t base = (size_t)blockIdx.x * 2048 + threadIdx.x;
    float4 a = __ldcs(src + base);
    float4 b = __ldcs(src + base + 512);
    float4 c = __ldcs(src + base + 1024);
    float4 d = __ldcs(src + base + 1536);
    __stcs(dst + base,        a);
    __stcs(dst + base + 512,  b);
    __stcs(dst + base + 1024, c);
    __stcs(dst + base + 1536, d);
}

// ---------------------------------------------------------------------------
// Kernel 3: bucket-ordered scatter-max + zero out[:,:,1].
// tid = (b*S + s)*A + rank. A warp covers 32 consecutive bucket-ordered
// ranks of one (b,s) row -> atomics land in a narrow ascending vocab window
// (DRAM-row friendly). atomicMax result unused -> RED. Non-negative floats:
// int max == float max. Zeroing col 1 is safe: no atomic targets m==1.
// ---------------------------------------------------------------------------
__global__ void __launch_bounds__(512)
pg_scatter_kernel(const float* __restrict__ att, float* __restrict__ out) {
    unsigned tid  = blockIdx.x * blockDim.x + threadIdx.x;  // 0 .. 524287
    unsigned rank = tid & (AA - 1);
    unsigned bs   = tid >> 9;          // b*S + s  (0 .. 1023)
    unsigned b    = bs >> 5;

    if (tid < BB * SS) {
        out[(size_t)tid * VOCAB + 1] = 0.0f;     // out[:, :, 1] = 0
    }

    int packed = g_sorted[(b << 9) | rank];
    if (packed != SENTINEL) {
        int m = packed >> 9;
        int a = packed & (AA - 1);
        float v = att[(size_t)bs * AA + a];
        atomicMax((int*)out + (size_t)bs * VOCAB + m, __float_as_int(v));
    }
}

// ---------------------------------------------------------------------------
// Launch
// Inputs (metadata order):
//   d_in[0] decoder_outputs  f32 [B,S,VOCAB]
//   d_in[1] attention_scores f32 [B,S,A]
//   d_in[2] input_sequence   i32 [B,A]
//   d_in[3] repeat_idx       i32 [S,1]   (unused)
//   d_in[4] repeat_idx2      i32 [B,1]   (unused)
//   d_in[5] convert_table    i32 [SRC_VOCAB]
// Output: f32 [B,S,VOCAB]
// ---------------------------------------------------------------------------
extern "C" void kernel_launch(void* const* d_in, const int* in_sizes, int n_in,
                              void* d_out, int out_size) {
    const float4* dec = (const float4*)d_in[0];
    const float*  att = (const float*)d_in[1];
    const int*    seq = (const int*)d_in[2];
    const int*    tbl = (const int*)d_in[5];
    float*        out = (float*)d_out;

    pg_sort_kernel<<<BB, AA>>>(seq, tbl);                      // no out dep

    const int n4 = BB * SS * VOCAB / 4;                        // 8,192,000
    pg_copy_kernel<<<n4 / 2048, 512>>>(dec, (float4*)out);

    pg_scatter_kernel<<<(BB * SS * AA) / 512, 512>>>(att, out);
}